// round 5
// baseline (speedup 1.0000x reference)
#include <cuda_runtime.h>
#include <math.h>
#include <stdint.h>

#define NN 50000
#define FF 128
#define CC 512
#define EE 800000
#define HH 256

#define OFF_ADJ   (CC*FF)
#define OFF_BATCH (OFF_ADJ + CC*CC)
#define OFF_S     (OFF_BATCH + CC)

// ---------------- scratch ----------------------------------------------------
__device__ __align__(16) float g_h[(size_t)NN * CC];   // wide buffer (512)
__device__ __align__(16) float g_z[(size_t)NN * HH];   // 256 buffer
__device__ __align__(16) float g_t[(size_t)NN * HH];   // 256 buffer
__device__ float g_inv[NN];
__device__ int   g_deg[NN];
__device__ int   g_off[NN + 1];
__device__ int   g_cur[NN];
__device__ int   g_csr_src[EE];
__device__ float g_csr_cf[EE];
__device__ int   g_cluster[NN];
__device__ float g_hs[NN];
__device__ int   g_sdeg[NN];
__device__ float g_invs[NN];
__device__ float g_sagg[NN];
__device__ float g_score[NN];
__device__ int   g_icnt[CC];
__device__ int   g_segkey[CC];
__device__ int   g_segidx[CC];
__device__ int   g_bsum[256];
__device__ int   g_bpref[256];

__device__ __forceinline__ int fkey(float f) {
    int b = __float_as_int(f);
    return b < 0 ? (b ^ 0x7FFFFFFF) : b;
}
__device__ __forceinline__ float fdec(int k) {
    return __int_as_float(k < 0 ? (k ^ 0x7FFFFFFF) : k);
}

// ---------------- init / degree ----------------------------------------------
__global__ void k_init(float* out) {
    int i = blockIdx.x * blockDim.x + threadIdx.x;
    int stride = gridDim.x * blockDim.x;
    for (int j = i; j < NN; j += stride) { g_deg[j] = 0; g_sdeg[j] = 0; g_sagg[j] = 0.f; }
    for (int j = i; j < CC; j += stride) {
        g_icnt[j] = 0; g_segkey[j] = (int)0x80000000; g_segidx[j] = NN;
        out[OFF_BATCH + j] = 0.f;
    }
    for (int j = i; j < CC * CC; j += stride) out[OFF_ADJ + j] = 0.f;
}

__global__ void k_deg(const int* __restrict__ ei) {
    int e = blockIdx.x * blockDim.x + threadIdx.x;
    if (e < EE) atomicAdd(&g_deg[ei[EE + e]], 1);
}

// ---------------- scan (3 phases; phase1 also computes g_inv) ----------------
__global__ void __launch_bounds__(256) k_scan1() {
    __shared__ int s[256];
    int t = threadIdx.x;
    int i = blockIdx.x * 256 + t;
    int v = (i < NN) ? g_deg[i] : 0;
    if (i < NN) g_inv[i] = rsqrtf((float)v + 1.0f);
    s[t] = v;
    __syncthreads();
    for (int off = 1; off < 256; off <<= 1) {
        int u = (t >= off) ? s[t - off] : 0;
        __syncthreads();
        s[t] += u;
        __syncthreads();
    }
    if (i < NN) g_off[i] = s[t] - v;
    if (t == 255) g_bsum[blockIdx.x] = s[255];
}
__global__ void __launch_bounds__(256) k_scan2(int nblocks) {
    __shared__ int s[256];
    int t = threadIdx.x;
    int v = (t < nblocks) ? g_bsum[t] : 0;
    s[t] = v;
    __syncthreads();
    for (int off = 1; off < 256; off <<= 1) {
        int u = (t >= off) ? s[t - off] : 0;
        __syncthreads();
        s[t] += u;
        __syncthreads();
    }
    g_bpref[t] = s[t] - v;
    if (t == 255) g_off[NN] = s[255];
}
__global__ void __launch_bounds__(256) k_scan3() {
    int i = blockIdx.x * 256 + threadIdx.x;
    if (i < NN) {
        int o = g_off[i] + g_bpref[blockIdx.x];
        g_off[i] = o;
        g_cur[i] = o;
    }
}

__global__ void k_fill(const int* __restrict__ ei) {
    int e = blockIdx.x * blockDim.x + threadIdx.x;
    if (e >= EE) return;
    int s = ei[e], d = ei[EE + e];
    int p = atomicAdd(&g_cur[d], 1);
    g_csr_src[p] = s;
    g_csr_cf[p] = g_inv[s] * g_inv[d];
}

// ---------------- split-tf32 tensor-core GEMM --------------------------------
__device__ __forceinline__ uint32_t f2tf(float f) {
    uint32_t r;
    asm("cvt.rna.tf32.f32 %0, %1;" : "=r"(r) : "f"(f));
    return r;
}
__device__ __forceinline__ void mma_tf32(float4& d,
                                         uint32_t a0, uint32_t a1, uint32_t a2, uint32_t a3,
                                         uint32_t b0, uint32_t b1) {
    asm volatile("mma.sync.aligned.m16n8k8.row.col.f32.tf32.tf32.f32 "
                 "{%0,%1,%2,%3}, {%4,%5,%6,%7}, {%8,%9}, {%0,%1,%2,%3};"
                 : "+f"(d.x), "+f"(d.y), "+f"(d.z), "+f"(d.w)
                 : "r"(a0), "r"(a1), "r"(a2), "r"(a3), "r"(b0), "r"(b1));
}

#define TCSTRIDE 136

__global__ void __launch_bounds__(256) k_tcgemm(const float* __restrict__ A,
                                                const float* __restrict__ B,
                                                const float* __restrict__ bias,
                                                float* __restrict__ Cm,
                                                int M, int K, int Nc, int epi) {
    __shared__ uint32_t Ah[2][8][TCSTRIDE];
    __shared__ uint32_t Al[2][8][TCSTRIDE];
    __shared__ uint32_t Bh[2][8][TCSTRIDE];
    __shared__ uint32_t Bl[2][8][TCSTRIDE];

    const int tid = threadIdx.x;
    const int wid = tid >> 5;
    const int lane = tid & 31;
    const int q = lane >> 2;
    const int t4 = lane & 3;
    const int wm = wid & 3;
    const int wn = wid >> 2;
    const int m0 = wm * 32;
    const int n0 = wn * 64;

    const int rowBase = blockIdx.y * 128;
    const int colBase = blockIdx.x * 128;

    const int ar = tid >> 1;
    const int ac4 = (tid & 1) * 4;
    const int br = tid >> 5;
    const int bc4 = (tid & 31) * 4;
    const bool aok = (rowBase + ar) < M;
    const float* Aptr = A + (size_t)(rowBase + ar) * K + ac4;
    const float* Bptr = B + (size_t)br * Nc + colBase + bc4;

    float4 acc[2][8];
#pragma unroll
    for (int mi = 0; mi < 2; mi++)
#pragma unroll
        for (int ni = 0; ni < 8; ni++) acc[mi][ni] = make_float4(0.f, 0.f, 0.f, 0.f);

#define SPLIT_STORE(arrH, arrL, BUF, D0, D1, V)                      \
    {                                                                \
        uint32_t h_ = f2tf(V);                                       \
        float lo_ = (V) - __uint_as_float(h_);                       \
        arrH[BUF][D0][D1] = h_;                                      \
        arrL[BUF][D0][D1] = f2tf(lo_);                               \
    }
#define LOAD_TILE(BUF, K0)                                                        \
    {                                                                             \
        float4 va = aok ? *(const float4*)(Aptr + (K0))                           \
                        : make_float4(0.f, 0.f, 0.f, 0.f);                        \
        float4 vb = *(const float4*)(Bptr + (size_t)(K0) * Nc);                   \
        SPLIT_STORE(Ah, Al, BUF, ac4 + 0, ar, va.x)                               \
        SPLIT_STORE(Ah, Al, BUF, ac4 + 1, ar, va.y)                               \
        SPLIT_STORE(Ah, Al, BUF, ac4 + 2, ar, va.z)                               \
        SPLIT_STORE(Ah, Al, BUF, ac4 + 3, ar, va.w)                               \
        SPLIT_STORE(Bh, Bl, BUF, br, bc4 + 0, vb.x)                               \
        SPLIT_STORE(Bh, Bl, BUF, br, bc4 + 1, vb.y)                               \
        SPLIT_STORE(Bh, Bl, BUF, br, bc4 + 2, vb.z)                               \
        SPLIT_STORE(Bh, Bl, BUF, br, bc4 + 3, vb.w)                               \
    }

#define COMPUTE_TILE(BUF)                                                          \
    {                                                                              \
        uint32_t ah[2][4], al[2][4];                                               \
        _Pragma("unroll")                                                          \
        for (int mi = 0; mi < 2; mi++) {                                           \
            int mrow = m0 + mi * 16;                                               \
            ah[mi][0] = Ah[BUF][t4][mrow + q];                                     \
            ah[mi][1] = Ah[BUF][t4][mrow + q + 8];                                 \
            ah[mi][2] = Ah[BUF][t4 + 4][mrow + q];                                 \
            ah[mi][3] = Ah[BUF][t4 + 4][mrow + q + 8];                             \
            al[mi][0] = Al[BUF][t4][mrow + q];                                     \
            al[mi][1] = Al[BUF][t4][mrow + q + 8];                                 \
            al[mi][2] = Al[BUF][t4 + 4][mrow + q];                                 \
            al[mi][3] = Al[BUF][t4 + 4][mrow + q + 8];                             \
        }                                                                          \
        _Pragma("unroll")                                                          \
        for (int ni = 0; ni < 8; ni++) {                                           \
            int ncol = n0 + ni * 8 + q;                                            \
            uint32_t bh0 = Bh[BUF][t4][ncol];                                      \
            uint32_t bh1 = Bh[BUF][t4 + 4][ncol];                                  \
            uint32_t bl0 = Bl[BUF][t4][ncol];                                      \
            uint32_t bl1 = Bl[BUF][t4 + 4][ncol];                                  \
            _Pragma("unroll")                                                      \
            for (int mi = 0; mi < 2; mi++) {                                       \
                mma_tf32(acc[mi][ni], ah[mi][0], ah[mi][1], ah[mi][2], ah[mi][3],  \
                         bh0, bh1);                                                \
                mma_tf32(acc[mi][ni], ah[mi][0], ah[mi][1], ah[mi][2], ah[mi][3],  \
                         bl0, bl1);                                                \
                mma_tf32(acc[mi][ni], al[mi][0], al[mi][1], al[mi][2], al[mi][3],  \
                         bh0, bh1);                                                \
            }                                                                      \
        }                                                                          \
    }

    LOAD_TILE(0, 0)
    __syncthreads();

    int buf = 0;
    for (int k0 = 8; k0 < K; k0 += 8) {
        COMPUTE_TILE(buf)
        LOAD_TILE(buf ^ 1, k0)
        __syncthreads();
        buf ^= 1;
    }
    COMPUTE_TILE(buf)

#pragma unroll
    for (int mi = 0; mi < 2; mi++) {
#pragma unroll
        for (int ni = 0; ni < 8; ni++) {
            int col = colBase + n0 + ni * 8 + 2 * t4;
            float bb0 = 0.f, bb1 = 0.f;
            if (epi) { bb0 = bias[col]; bb1 = bias[col + 1]; }
            int r0 = rowBase + m0 + mi * 16 + q;
            int r1 = r0 + 8;
            float4 v = acc[mi][ni];
            float o0 = v.x + bb0, o1 = v.y + bb1, o2 = v.z + bb0, o3 = v.w + bb1;
            if (epi) {
                o0 = fmaxf(o0, 0.f); o1 = fmaxf(o1, 0.f);
                o2 = fmaxf(o2, 0.f); o3 = fmaxf(o3, 0.f);
            }
            if (r0 < M) *(float2*)(Cm + (size_t)r0 * Nc + col) = make_float2(o0, o1);
            if (r1 < M) *(float2*)(Cm + (size_t)r1 * Nc + col) = make_float2(o2, o3);
        }
    }
}

// ---------------- aggregation: block per node, smem-staged (proven best) -----
template <bool EPI>
__global__ void __launch_bounds__(256) k_agg256(const float* __restrict__ h,
                                                float* __restrict__ z,
                                                const float* __restrict__ bias) {
    int i = blockIdx.x;
    int t = threadIdx.x;
    int beg = g_off[i], end = g_off[i + 1];
    float inv = g_inv[i];
    float acc = inv * inv * __ldg(h + (size_t)i * HH + t);

    __shared__ int   s_src[128];
    __shared__ float s_cf[128];
    for (int e0 = beg; e0 < end; e0 += 128) {
        int m = min(128, end - e0);
        __syncthreads();
        if (t < m) {
            s_src[t] = g_csr_src[e0 + t];
            s_cf[t]  = g_csr_cf[e0 + t];
        }
        __syncthreads();
        int j = 0;
        for (; j + 4 <= m; j += 4) {
            const float* r0 = h + (size_t)s_src[j + 0] * HH + t;
            const float* r1 = h + (size_t)s_src[j + 1] * HH + t;
            const float* r2 = h + (size_t)s_src[j + 2] * HH + t;
            const float* r3 = h + (size_t)s_src[j + 3] * HH + t;
            float c0 = s_cf[j + 0], c1 = s_cf[j + 1];
            float c2 = s_cf[j + 2], c3 = s_cf[j + 3];
            float v0 = __ldg(r0), v1 = __ldg(r1), v2 = __ldg(r2), v3 = __ldg(r3);
            acc = fmaf(c0, v0, acc);
            acc = fmaf(c1, v1, acc);
            acc = fmaf(c2, v2, acc);
            acc = fmaf(c3, v3, acc);
        }
        for (; j < m; j++)
            acc = fmaf(s_cf[j], __ldg(h + (size_t)s_src[j] * HH + t), acc);
    }
    if (EPI) acc = fmaxf(acc + bias[t], 0.f);
    z[(size_t)i * HH + t] = acc;
}

// ---------------- softmax + argmax (warp-shuffle reductions) -----------------
__global__ void __launch_bounds__(256) k_softmax(const float* __restrict__ logits,
                                                 float* __restrict__ S) {
    int i = blockIdx.x;
    int t = threadIdx.x;
    int w = t >> 5, lane = t & 31;
    const float* row = logits + (size_t)i * CC;
    float v0 = row[t], v1 = row[t + 256];
    float bv = v0; int bi = t;
    if (v1 > bv) { bv = v1; bi = t + 256; }

#pragma unroll
    for (int off = 16; off > 0; off >>= 1) {
        float ov = __shfl_xor_sync(0xFFFFFFFF, bv, off);
        int   oi = __shfl_xor_sync(0xFFFFFFFF, bi, off);
        if (ov > bv || (ov == bv && oi < bi)) { bv = ov; bi = oi; }
    }
    __shared__ float swv[8];
    __shared__ int   swi[8];
    if (lane == 0) { swv[w] = bv; swi[w] = bi; }
    __syncthreads();
    float m = swv[0]; int am = swi[0];
#pragma unroll
    for (int k = 1; k < 8; k++) {
        float ov = swv[k]; int oi = swi[k];
        if (ov > m || (ov == m && oi < am)) { m = ov; am = oi; }
    }
    if (t == 0) g_cluster[i] = am;

    float e0 = expf(v0 - m), e1 = expf(v1 - m);
    float s = e0 + e1;
#pragma unroll
    for (int off = 16; off > 0; off >>= 1)
        s += __shfl_xor_sync(0xFFFFFFFF, s, off);
    __shared__ float sws[8];
    if (lane == 0) sws[w] = s;
    __syncthreads();
    float tot = sws[0] + sws[1] + sws[2] + sws[3] + sws[4] + sws[5] + sws[6] + sws[7];
    float invsum = 1.0f / tot;
    S[(size_t)i * CC + t]       = e0 * invsum;
    S[(size_t)i * CC + t + 256] = e1 * invsum;
}

// ---------------- score layer -------------------------------------------------
__global__ void k_hs(const float* __restrict__ x, const float* __restrict__ Ws) {
    int g = blockIdx.x * blockDim.x + threadIdx.x;
    int w = g >> 5, lane = g & 31;
    if (w >= NN) return;
    float4 xv = __ldg((const float4*)x + (size_t)w * 32 + lane);
    float4 wv = __ldg((const float4*)Ws + lane);
    float s = xv.x * wv.x + xv.y * wv.y + xv.z * wv.z + xv.w * wv.w;
#pragma unroll
    for (int off = 16; off > 0; off >>= 1) s += __shfl_down_sync(0xFFFFFFFF, s, off);
    if (lane == 0) g_hs[w] = s;
}

__global__ void k_intradeg(const int* __restrict__ ei) {
    int e = blockIdx.x * blockDim.x + threadIdx.x;
    if (e >= EE) return;
    int s = ei[e], d = ei[EE + e];
    int cs = g_cluster[s], cd = g_cluster[d];
    if (cs == cd) {
        atomicAdd(&g_sdeg[d], 1);
        atomicAdd(&g_icnt[cs], 1);
    }
}

__global__ void k_invs() {
    int i = blockIdx.x * blockDim.x + threadIdx.x;
    if (i < NN) g_invs[i] = rsqrtf((float)g_sdeg[i] + 1.0f);
}

__global__ void k_sagg(const int* __restrict__ ei) {
    int e = blockIdx.x * blockDim.x + threadIdx.x;
    if (e >= EE) return;
    int s = ei[e], d = ei[EE + e];
    if (g_cluster[s] == g_cluster[d])
        atomicAdd(&g_sagg[d], g_invs[s] * g_invs[d] * g_hs[s]);
}

// score + fused segmax
__global__ void k_score(const float* __restrict__ bs) {
    int i = blockIdx.x * blockDim.x + threadIdx.x;
    if (i >= NN) return;
    float inv = g_invs[i];
    float v = g_sagg[i] + inv * inv * g_hs[i] + bs[0];
    float sc = tanhf(v);
    g_score[i] = sc;
    atomicMax(&g_segkey[g_cluster[i]], fkey(sc));
}

__global__ void k_segidx() {
    int i = blockIdx.x * blockDim.x + threadIdx.x;
    if (i >= NN) return;
    int c = g_cluster[i];
    float mx = fdec(g_segkey[c]);
    if (g_score[i] >= mx) atomicMin(&g_segidx[c], i);
}

// ---------------- pooling + adjacency ----------------------------------------
__global__ void __launch_bounds__(128) k_pool(const float* __restrict__ x,
                                              float* __restrict__ out) {
    int c = blockIdx.x;
    bool ne = g_icnt[c] > 0;
    float alpha = ne ? fdec(g_segkey[c]) : 0.f;
    int idx = min(g_segidx[c], NN - 1);
    out[(size_t)c * FF + threadIdx.x] = x[(size_t)idx * FF + threadIdx.x] * alpha;
}

__global__ void k_adj(const int* __restrict__ ei, float* __restrict__ out) {
    int e = blockIdx.x * blockDim.x + threadIdx.x;
    if (e >= EE) return;
    int cs = g_cluster[ei[e]], cd = g_cluster[ei[EE + e]];
    if (cs != cd && g_icnt[cs] > 0 && g_icnt[cd] > 0) {
        float* cell = out + OFF_ADJ + (size_t)cs * CC + cd;
        if (*cell == 0.f) *cell = 1.0f;     // idempotent; dedups write traffic
    }
}

// ---------------- launch ------------------------------------------------------
extern "C" void kernel_launch(void* const* d_in, const int* in_sizes, int n_in,
                              void* d_out, int out_size) {
    const float* x   = (const float*)d_in[0];
    const int*   ei  = (const int*)d_in[1];
    const float* W1  = (const float*)d_in[3];
    const float* b1  = (const float*)d_in[4];
    const float* W2  = (const float*)d_in[5];
    const float* b2  = (const float*)d_in[6];
    const float* W3  = (const float*)d_in[7];
    const float* b3  = (const float*)d_in[8];
    const float* Ws  = (const float*)d_in[9];
    const float* bs  = (const float*)d_in[10];
    float* out = (float*)d_out;

    const int EB = (EE + 255) / 256;
    const int NB = (NN + 255) / 256;

    k_init<<<512, 256>>>(out);                                      // 0
    k_deg<<<EB, 256>>>(ei);                                         // 1
    k_scan1<<<NB, 256>>>();                                         // 2 (+inv)
    {                                                               // 3: h1 = x @ W1  [PROFILED]
        dim3 g(HH / 128, (NN + 127) / 128);
        k_tcgemm<<<g, 256>>>(x, W1, (const float*)0, g_z, NN, FF, HH, 0);
    }
    k_scan2<<<1, 256>>>(NB);                                        // 4
    k_scan3<<<NB, 256>>>();                                         // 5
    k_fill<<<EB, 256>>>(ei);                                        // 6

    // layer 1: z1 = relu(agg(h1) + b1)    (g_z -> g_t)
    k_agg256<true><<<NN, 256>>>(g_z, g_t, b1);
    // layer 2: a2 = agg(z1); h2 = relu(a2 @ W2 + b2)   (g_t -> g_z -> g_t)
    k_agg256<false><<<NN, 256>>>(g_t, g_z, (const float*)0);
    {
        dim3 g(HH / 128, (NN + 127) / 128);
        k_tcgemm<<<g, 256>>>(g_z, W2, b2, g_t, NN, HH, HH, 1);
    }
    // layer 3: a3 = agg(h2); logits = relu(a3 @ W3 + b3)  (g_t -> g_z -> g_h)
    k_agg256<false><<<NN, 256>>>(g_t, g_z, (const float*)0);
    {
        dim3 g(CC / 128, (NN + 127) / 128);
        k_tcgemm<<<g, 256>>>(g_z, W3, b3, g_h, NN, HH, CC, 1);
    }

    k_softmax<<<NN, 256>>>(g_h, out + OFF_S);

    k_hs<<<(NN * 32 + 255) / 256, 256>>>(x, Ws);
    k_intradeg<<<EB, 256>>>(ei);
    k_invs<<<NB, 256>>>();
    k_sagg<<<EB, 256>>>(ei);
    k_score<<<NB, 256>>>(bs);
    k_segidx<<<NB, 256>>>();
    k_pool<<<CC, 128>>>(x, out);
    k_adj<<<EB, 256>>>(ei, out);

    (void)in_sizes; (void)n_in; (void)out_size;
}